// round 17
// baseline (speedup 1.0000x reference)
#include <cuda_runtime.h>
#include <cuda_fp16.h>
#include <cstdint>

#define EE 800000
#define NN 50000
#define FULL 0xFFFFFFFFu

#define TE_S 128
#define NBLK_S (EE / TE_S)   // 6250
#define TE_V 128
#define NBLK_V (EE / TE_V)   // 6250

// ---------------- scratch (device globals; no allocation) ----------------
__device__ float g_score[(size_t)EE * 4];   // exp(score) per edge/head
__device__ float g_denom[NN * 4];           // segment_sum(exp(score))
__device__ uint2 g_wfrag[3 * 8 * 4 * 32];   // [mat][n][ks][lane] = {wh0, wh1} fp16

// ---------------- smem layouts (bytes) ----------------
#define XW 36                                 // words per X row (64 fp16 + pad)
#define XTILE (128 * 144)
// score kernel: Xq, Xk only (36.9 KB)
#define OFF_XQ 0
#define OFF_XK (XTILE)
#define SMEM_A (2 * XTILE)
// value kernel: Xv only (18.4 KB)
#define SMEM_B (XTILE)

// ---------------- helpers ----------------
__device__ __forceinline__ uint32_t pack_h2(float a, float b) {
    __half2 h = __floats2half2_rn(a, b);
    return *(uint32_t *)&h;
}

__device__ __forceinline__ void mma_f16(float c[4], const uint32_t a[4],
                                        uint32_t b0, uint32_t b1) {
    asm volatile(
        "mma.sync.aligned.m16n8k16.row.col.f32.f16.f16.f32 "
        "{%0,%1,%2,%3}, {%4,%5,%6,%7}, {%8,%9}, {%0,%1,%2,%3};"
        : "+f"(c[0]), "+f"(c[1]), "+f"(c[2]), "+f"(c[3])
        : "r"(a[0]), "r"(a[1]), "r"(a[2]), "r"(a[3]), "r"(b0), "r"(b1));
}

// warp-local staging: warp stages ITS OWN 16 rows [rbase, rbase+16) -> fp16 smem
__device__ __forceinline__ void stage_own(const float *__restrict__ gsrc, long gbase,
                                          uint32_t *X, int rbase, int lane) {
#pragma unroll
    for (int it = 0; it < 8; it++) {
        int idx = lane + it * 32;           // over 256 float4 (16 rows x 16)
        int row = rbase + (idx >> 4);
        int c4 = idx & 15;
        float4 x = ((const float4 *)(gsrc + (gbase + row) * 64))[c4];
        uint2 wrd;
        wrd.x = pack_h2(x.x, x.y);
        wrd.y = pack_h2(x.z, x.w);
        ((uint2 *)(X + row * XW))[c4] = wrd;
    }
}

// 16-edge m-tile projection, W fragments read from GLOBAL (L1-hot): acc[8][4]
__device__ __forceinline__ void proj_tile_g(const uint32_t *X, const uint2 *wgbase,
                                            int rbase, int g, int qd, int lane,
                                            float acc[8][4]) {
#pragma unroll
    for (int n = 0; n < 8; n++)
#pragma unroll
        for (int c = 0; c < 4; c++) acc[n][c] = 0.0f;
#pragma unroll
    for (int ks = 0; ks < 4; ks++) {
        uint32_t a[4];
        int wb = (rbase + g) * XW + qd + ks * 8;
        a[0] = X[wb];          a[1] = X[wb + 8 * XW];
        a[2] = X[wb + 4];      a[3] = X[wb + 8 * XW + 4];
        const uint2 *wrow = wgbase + ks * 32 + lane;
#pragma unroll
        for (int n = 0; n < 8; n++) {
            uint2 F = __ldg(&wrow[n * 128]);
            mma_f16(acc[n], a, F.x, F.y);
        }
    }
}

// ---------------- W prep (fp16, fragment order) + denom zeroing ----------
__global__ void prep_kernel(const float *__restrict__ Wq,
                            const float *__restrict__ Wk,
                            const float *__restrict__ Wv) {
    int t = blockIdx.x * blockDim.x + threadIdx.x;
    if (t < 3072) {
        int lane = t & 31;
        int ks = (t >> 5) & 3;
        int n = (t >> 7) & 7;
        int m = t >> 10;
        const float *W = (m == 0) ? Wq : (m == 1) ? Wk : Wv;
        int j = n * 8 + (lane >> 2);
        int k0 = 2 * (lane & 3) + 16 * ks;
        uint2 f;
        f.x = pack_h2(W[(k0 + 0) * 64 + j], W[(k0 + 1) * 64 + j]);
        f.y = pack_h2(W[(k0 + 8) * 64 + j], W[(k0 + 9) * 64 + j]);
        g_wfrag[t] = f;
    }
    if (t < NN * 4) g_denom[t] = 0.0f;
}

// ---------------- score pass: q,k (1-term fp16) -> exp + denom ------------
// Warp-autonomous: no __syncthreads; each warp stages its own rows.
// softmax identity: exp(s-m)/(sum exp(s'-m) + exp(-m)) == exp(s)/(sum exp(s') + 1)
__global__ __launch_bounds__(256, 3) void score_kernel(
    const float *__restrict__ q, const float *__restrict__ k,
    const float *__restrict__ bq, const float *__restrict__ bk,
    const int *__restrict__ index) {
    extern __shared__ char smem[];
    uint32_t *Xq = (uint32_t *)(smem + OFF_XQ);
    uint32_t *Xk = (uint32_t *)(smem + OFF_XK);

    const int tid = threadIdx.x;
    const int w = tid >> 5;
    const int lane = tid & 31;
    const int g = lane >> 2;
    const int qd = lane & 3;
    const long gbase = (long)blockIdx.x * TE_S;
    const int rbase = w * 16;

    stage_own(q, gbase, Xq, rbase, lane);
    stage_own(k, gbase, Xk, rbase, lane);
    __syncwarp();

    float accQ[8][4], accK[8][4];
    proj_tile_g(Xq, g_wfrag + 0, rbase, g, qd, lane, accQ);
    proj_tile_g(Xk, g_wfrag + 1024, rbase, g, qd, lane, accK);

    // bias add (global, L1-hot broadcast) + per-head scores
#pragma unroll
    for (int n = 0; n < 8; n++) {
        int j0 = n * 8 + qd * 2;
        float bq0 = __ldg(&bq[j0]), bq1 = __ldg(&bq[j0 + 1]);
        float bk0 = __ldg(&bk[j0]), bk1 = __ldg(&bk[j0 + 1]);
        accQ[n][0] += bq0; accQ[n][1] += bq1;
        accQ[n][2] += bq0; accQ[n][3] += bq1;
        accK[n][0] += bk0; accK[n][1] += bk1;
        accK[n][2] += bk0; accK[n][3] += bk1;
    }

    float sc[2][4];
#pragma unroll
    for (int half = 0; half < 2; half++)
#pragma unroll
        for (int h = 0; h < 4; h++) {
            float p = 0.0f;
#pragma unroll
            for (int dn = 0; dn < 2; dn++) {
                int n = 2 * h + dn;
                p += accQ[n][half * 2] * accK[n][half * 2] +
                     accQ[n][half * 2 + 1] * accK[n][half * 2 + 1];
            }
            p += __shfl_xor_sync(FULL, p, 1);
            p += __shfl_xor_sync(FULL, p, 2);
            sc[half][h] = p;
        }

#pragma unroll
    for (int half = 0; half < 2; half++) {
        long e = gbase + rbase + half * 8 + g;
        float s = (qd & 2) ? ((qd & 1) ? sc[half][3] : sc[half][2])
                           : ((qd & 1) ? sc[half][1] : sc[half][0]);
        float exv = __expf(s * 0.25f);
        g_score[e * 4 + qd] = exv;

        // warp-aggregated segmented atomicAdd over contiguous same-index runs
        int nidx = index[e];
        float sum = exv;
#pragma unroll
        for (int off = 4; off < 32; off <<= 1) {
            float o = __shfl_down_sync(FULL, sum, off);
            int no = __shfl_down_sync(FULL, nidx, off);
            if (lane + off < 32 && no == nidx) sum += o;
        }
        int nprev = __shfl_up_sync(FULL, nidx, 4);
        bool leader = (g == 0) || (nprev != nidx);
        if (leader)
            atomicAdd(&g_denom[nidx * 4 + qd], sum);
    }
}

// ---------------- value pass: V projection (pure fp16) * attn -> out ------
// Warp-autonomous: no __syncthreads.
__global__ __launch_bounds__(256, 4) void value_kernel(
    const float *__restrict__ v, const float *__restrict__ bv,
    const int *__restrict__ index, float *__restrict__ out) {
    extern __shared__ char smem[];
    uint32_t *X = (uint32_t *)smem;

    const int tid = threadIdx.x;
    const int w = tid >> 5;
    const int lane = tid & 31;
    const int g = lane >> 2;
    const int qd = lane & 3;
    const long gbase = (long)blockIdx.x * TE_V;
    const int rbase = w * 16;

    stage_own(v, gbase, X, rbase, lane);

    // attn = ex / (denom_sum + 1); fetch during staging
    const long e0 = gbase + rbase + g;   // rows e0, e0+8
    float att[2][4];
#pragma unroll
    for (int r = 0; r < 2; r++) {
        long e = e0 + r * 8;
        int n = index[e];
        float4 ex = ((const float4 *)g_score)[e];
        float4 dn = ((const float4 *)g_denom)[n];
        att[r][0] = __fdividef(ex.x, dn.x + 1.0f);
        att[r][1] = __fdividef(ex.y, dn.y + 1.0f);
        att[r][2] = __fdividef(ex.z, dn.z + 1.0f);
        att[r][3] = __fdividef(ex.w, dn.w + 1.0f);
    }

    __syncwarp();

    float acc[8][4];
    proj_tile_g(X, g_wfrag + 2048, rbase, g, qd, lane, acc);

#pragma unroll
    for (int n = 0; n < 8; n++) {
        int h = n >> 1;
        int j0 = n * 8 + qd * 2;
        float b0 = __ldg(&bv[j0]), b1 = __ldg(&bv[j0 + 1]);
        float2 v0, v1;
        v0.x = att[0][h] * (acc[n][0] + b0);
        v0.y = att[0][h] * (acc[n][1] + b1);
        v1.x = att[1][h] * (acc[n][2] + b0);
        v1.y = att[1][h] * (acc[n][3] + b1);
        *(float2 *)(out + (size_t)e0 * 64 + j0) = v0;
        *(float2 *)(out + (size_t)(e0 + 8) * 64 + j0) = v1;
    }
}

// ---------------- launcher ----------------
extern "C" void kernel_launch(void *const *d_in, const int *in_sizes, int n_in,
                              void *d_out, int out_size) {
    const float *q = (const float *)d_in[0];
    const float *k = (const float *)d_in[1];
    const float *v = (const float *)d_in[2];
    const float *Wq = (const float *)d_in[3];
    const float *bq = (const float *)d_in[4];
    const float *Wk = (const float *)d_in[5];
    const float *bk = (const float *)d_in[6];
    const float *Wv = (const float *)d_in[7];
    const float *bv = (const float *)d_in[8];
    const int *index = (const int *)d_in[9];
    float *out = (float *)d_out;

    cudaFuncSetAttribute(score_kernel, cudaFuncAttributeMaxDynamicSharedMemorySize,
                         SMEM_A);
    cudaFuncSetAttribute(value_kernel, cudaFuncAttributeMaxDynamicSharedMemorySize,
                         SMEM_B);

    prep_kernel<<<(NN * 4 + 255) / 256, 256>>>(Wq, Wk, Wv);
    score_kernel<<<NBLK_S, 256, SMEM_A>>>(q, k, bq, bk, index);
    value_kernel<<<NBLK_V, 256, SMEM_B>>>(v, bv, index, out);
}